// round 5
// baseline (speedup 1.0000x reference)
#include <cuda_runtime.h>
#include <math.h>

#define H_DIM  2048
#define N_EXP  64
#define TOPK   8
#define KC     32      // K-chunk per smem stage
#define TILE_M 128     // tokens per block
#define NTHR   256

// fill phase: xs[128][32] (16KB, swizzled) + ws[32][64] (8KB, k-major) = 24KB
// epilogue reuses buffer as scores[128][65] = 33280B
#define SMEM_FLOATS (TILE_M * (N_EXP + 1))   // 8320 floats

// W transposed once per launch into k-major scratch: Wt[k][e]
__device__ float g_Wt[H_DIM * N_EXP];

__global__ void transpose_w_kernel(const float* __restrict__ w) {
    int idx = blockIdx.x * 256 + threadIdx.x;   // idx = k*64 + e (e fastest -> coalesced writes)
    if (idx < H_DIM * N_EXP) {
        int k = idx >> 6;
        int e = idx & 63;
        g_Wt[idx] = w[(size_t)e * H_DIM + k];
    }
}

typedef unsigned long long u64;

__global__ __launch_bounds__(NTHR) void moe_gate_kernel(
    const float* __restrict__ x,      // (T, H)
    float* __restrict__ out,
    int T, int two_outputs)
{
    __shared__ __align__(16) float smem[SMEM_FLOATS];
    float* xs  = smem;                     // [TILE_M][KC], swizzled
    float* wsm = smem + TILE_M * KC;       // [KC][N_EXP], k-major (expert-contiguous)
    float* sc  = smem;                     // [TILE_M][N_EXP+1] (epilogue reuse)

    const int tid = threadIdx.x;
    const int r   = tid >> 3;    // 0..31
    const int c   = tid & 7;     // 0..7
    const int tm  = r * 4;       // 4 token rows per thread
    const int tn  = c * 8;       // 8 expert cols per thread
    const int blk = blockIdx.x;

    const float* xblk = x + (size_t)blk * TILE_M * H_DIM;

    const int swa = ((tm >> 3) & 7) << 2;  // x-tile read swizzle (constant per thread)

    // fill-phase coordinates
    const int fm = tid >> 3;          // 0..31
    const int fk = (tid & 7) * 4;     // float4 column

    // accumulators: 4 tokens x 4 expert-pairs, packed f32x2
    u64 acc2[4][4];
    #pragma unroll
    for (int i = 0; i < 4; i++)
        #pragma unroll
        for (int j = 0; j < 4; j++) acc2[i][j] = 0ULL;

    // ---- prologue: prefetch first chunk into registers ----
    float4 px[4], pw[2];
    #pragma unroll
    for (int i = 0; i < 4; i++)
        px[i] = *(const float4*)(xblk + (size_t)(fm + i * 32) * H_DIM + fk);
    #pragma unroll
    for (int i = 0; i < 2; i++)
        pw[i] = *(const float4*)(&g_Wt[0] + tid * 4 + i * 1024);

    for (int k0 = 0; k0 < H_DIM; k0 += KC) {
        // ---- store prefetched chunk to smem ----
        #pragma unroll
        for (int i = 0; i < 4; i++) {
            int m = fm + i * 32;
            int ksw = fk ^ (((m >> 3) & 7) << 2);
            *(float4*)&xs[m * KC + ksw] = px[i];
        }
        #pragma unroll
        for (int i = 0; i < 2; i++)
            *(float4*)&wsm[tid * 4 + i * 1024] = pw[i];
        __syncthreads();

        // ---- prefetch next chunk (overlaps with compute below) ----
        int kn = k0 + KC;
        if (kn < H_DIM) {
            #pragma unroll
            for (int i = 0; i < 4; i++)
                px[i] = *(const float4*)(xblk + (size_t)(fm + i * 32) * H_DIM + kn + fk);
            #pragma unroll
            for (int i = 0; i < 2; i++)
                pw[i] = *(const float4*)(&g_Wt[(size_t)kn * N_EXP] + tid * 4 + i * 1024);
        }

        // ---- compute: packed f32x2 FFMA over expert pairs ----
        #pragma unroll
        for (int kk = 0; kk < KC; kk += 4) {
            float4 a4[4];
            #pragma unroll
            for (int i = 0; i < 4; i++)
                a4[i] = *(const float4*)&xs[(tm + i) * KC + (kk ^ swa)];
            #pragma unroll
            for (int q = 0; q < 4; q++) {
                const u64* bp = (const u64*)&wsm[(kk + q) * N_EXP + tn];
                u64 b0 = bp[0], b1 = bp[1], b2v = bp[2], b3v = bp[3];
                #pragma unroll
                for (int i = 0; i < 4; i++) {
                    float a = (q == 0) ? a4[i].x : (q == 1) ? a4[i].y
                            : (q == 2) ? a4[i].z : a4[i].w;
                    u64 ad;
                    asm("mov.b64 %0, {%1, %1};" : "=l"(ad) : "f"(a));
                    asm("fma.rn.f32x2 %0, %1, %2, %0;" : "+l"(acc2[i][0]) : "l"(ad), "l"(b0));
                    asm("fma.rn.f32x2 %0, %1, %2, %0;" : "+l"(acc2[i][1]) : "l"(ad), "l"(b1));
                    asm("fma.rn.f32x2 %0, %1, %2, %0;" : "+l"(acc2[i][2]) : "l"(ad), "l"(b2v));
                    asm("fma.rn.f32x2 %0, %1, %2, %0;" : "+l"(acc2[i][3]) : "l"(ad), "l"(b3v));
                }
            }
        }
        __syncthreads();
    }

    // ---- epilogue: unpack scores to smem, then 1 thread per token ----
    #pragma unroll
    for (int i = 0; i < 4; i++)
        #pragma unroll
        for (int j = 0; j < 4; j++) {
            float lo, hi;
            asm("mov.b64 {%0, %1}, %2;" : "=f"(lo), "=f"(hi) : "l"(acc2[i][j]));
            sc[(tm + i) * (N_EXP + 1) + tn + 2 * j]     = lo;
            sc[(tm + i) * (N_EXP + 1) + tn + 2 * j + 1] = hi;
        }
    __syncthreads();

    if (tid < TILE_M) {
        const float* row = &sc[tid * (N_EXP + 1)];

        float mx = row[0];
        #pragma unroll
        for (int e = 1; e < N_EXP; e++) mx = fmaxf(mx, row[e]);

        // top-8 on raw scores (softmax monotonic; denominator cancels under renorm).
        // Strict '>' => earliest index wins ties (matches lax.top_k).
        unsigned long long used = 0ULL;
        int   idxs[TOPK];
        float vals[TOPK];
        #pragma unroll
        for (int k = 0; k < TOPK; k++) {
            float best = -INFINITY;
            int   bi   = 0;
            for (int e = 0; e < N_EXP; e++) {
                if (!((used >> e) & 1ULL)) {
                    float v = row[e];
                    if (v > best) { best = v; bi = e; }
                }
            }
            used |= 1ULL << bi;
            idxs[k] = bi;
            vals[k] = best;
        }

        float ew[TOPK];
        float sumw = 0.0f;
        #pragma unroll
        for (int k = 0; k < TOPK; k++) {
            ew[k] = expf(vals[k] - mx);
            sumw += ew[k];
        }
        float inv = 1.0f / sumw;

        size_t t = (size_t)blk * TILE_M + tid;
        if (two_outputs) {
            #pragma unroll
            for (int k = 0; k < TOPK; k++) {
                out[t * TOPK + k] = (float)idxs[k];
                out[(size_t)T * TOPK + t * TOPK + k] = ew[k] * inv;
            }
        } else {
            #pragma unroll
            for (int k = 0; k < TOPK; k++)
                out[t * TOPK + k] = ew[k] * inv;
        }
    }
}

extern "C" void kernel_launch(void* const* d_in, const int* in_sizes, int n_in,
                              void* d_out, int out_size) {
    const float* x = (const float*)d_in[0];   // hidden_states (B,S,H) flattened
    const float* w = (const float*)d_in[1];   // weight (E,H)
    int T = in_sizes[0] / H_DIM;              // 16384
    int two = (out_size >= 2 * T * TOPK) ? 1 : 0;

    transpose_w_kernel<<<(H_DIM * N_EXP + 255) / 256, 256>>>(w);

    int grid = T / TILE_M;                    // 128
    moe_gate_kernel<<<grid, NTHR>>>(x, (float*)d_out, T, two);
}